// round 1
// baseline (speedup 1.0000x reference)
#include <cuda_runtime.h>
#include <cuda_bf16.h>

#define BATCH 4
#define SEQ   2048
#define NH    16
#define HD    64
#define HID   1024
#define QKV3  3072

// Scratch (static device globals — allocation-free per harness rules)
__device__ float g_qkv[BATCH * SEQ * QKV3];   // 96 MB: [b,s, 3*HID] (3,NH,HD packing)
__device__ float g_att[BATCH * SEQ * HID];    // 32 MB: attention output [b,s,h*64+d]
__device__ int   g_mask[BATCH * SEQ];         // canonical int mask

// ---------------------------------------------------------------------------
// Mask canonicalizer: the bool attention_mask's serialized dtype is unknown
// (int32 / float32 / uint8 / bf16). Detect from the first 32-bit word
// (mask[0] is True) and convert to int 0/1. Only reads within the smallest
// plausible buffer (8 KB) before deciding.
// ---------------------------------------------------------------------------
__global__ void mask_convert_kernel(const void* __restrict__ raw, int n) {
    __shared__ int mode;
    if (threadIdx.x == 0) {
        unsigned w0 = ((const unsigned*)raw)[0];
        if (w0 == 1u || w0 == 0u)           mode = 0;  // int32
        else if (w0 == 0x3F800000u)         mode = 1;  // float32
        else if (w0 == 0x01010101u)         mode = 2;  // uint8 (bool bytes)
        else if (w0 == 0x3F803F80u)         mode = 3;  // bf16 pair
        else                                 mode = 2;  // fallback: bytes
    }
    __syncthreads();
    int m = mode;
    for (int i = threadIdx.x; i < n; i += blockDim.x) {
        int v;
        if (m == 0)      v = (((const int*)raw)[i] != 0);
        else if (m == 1) v = (((const float*)raw)[i] != 0.0f);
        else if (m == 2) v = (((const unsigned char*)raw)[i] != 0);
        else { unsigned short h = ((const unsigned short*)raw)[i]; v = ((h & 0x7FFF) != 0); }
        g_mask[i] = v;
    }
}

// ---------------------------------------------------------------------------
// SGEMM: C[M,N] = A[M,K] @ B[K,N] (+ bias). 128x128x8 tiles, 256 threads,
// 8x8 register tile per thread. All dims divisible by tile sizes here.
// ---------------------------------------------------------------------------
template <bool BIAS>
__global__ __launch_bounds__(256, 2)
void sgemm128_kernel(const float* __restrict__ A, const float* __restrict__ B,
                     const float* __restrict__ bias, float* __restrict__ C,
                     int M, int N, int K) {
    __shared__ float As[8][128];   // transposed A tile: As[k][m]
    __shared__ float Bs[8][128];   // Bs[k][n]

    const int tid = threadIdx.x;
    const int tm  = tid >> 4;       // 0..15  row group (8 rows)
    const int tn  = tid & 15;       // 0..15  col group (8 cols)
    const int m0  = blockIdx.y * 128;
    const int n0  = blockIdx.x * 128;

    // A tile load: row = tid>>1 (0..127), 4 consecutive k at (tid&1)*4
    const int arow = tid >> 1;
    const int acol = (tid & 1) * 4;
    // B tile load: k row = tid>>5 (0..7), 4 consecutive n at (tid&31)*4
    const int brow = tid >> 5;
    const int bcol = (tid & 31) * 4;

    const float* Aptr = A + (size_t)(m0 + arow) * K + acol;
    const float* Bptr = B + (size_t)brow * N + n0 + bcol;

    float acc[8][8];
#pragma unroll
    for (int i = 0; i < 8; i++)
#pragma unroll
        for (int j = 0; j < 8; j++) acc[i][j] = 0.0f;

    for (int k0 = 0; k0 < K; k0 += 8) {
        float4 av = *(const float4*)Aptr;  Aptr += 8;
        float4 bv = *(const float4*)Bptr;  Bptr += (size_t)8 * N;

        As[acol + 0][arow] = av.x;
        As[acol + 1][arow] = av.y;
        As[acol + 2][arow] = av.z;
        As[acol + 3][arow] = av.w;
        *(float4*)&Bs[brow][bcol] = bv;
        __syncthreads();

#pragma unroll
        for (int kk = 0; kk < 8; kk++) {
            float a[8], b[8];
            *(float4*)&a[0] = *(const float4*)&As[kk][tm * 8];
            *(float4*)&a[4] = *(const float4*)&As[kk][tm * 8 + 4];
            *(float4*)&b[0] = *(const float4*)&Bs[kk][tn * 8];
            *(float4*)&b[4] = *(const float4*)&Bs[kk][tn * 8 + 4];
#pragma unroll
            for (int i = 0; i < 8; i++)
#pragma unroll
                for (int j = 0; j < 8; j++)
                    acc[i][j] = fmaf(a[i], b[j], acc[i][j]);
        }
        __syncthreads();
    }

#pragma unroll
    for (int i = 0; i < 8; i++) {
        float* crow = C + (size_t)(m0 + tm * 8 + i) * N + n0 + tn * 8;
        float4 o0, o1;
        if (BIAS) {
            const float* bp = bias + n0 + tn * 8;
            o0 = make_float4(acc[i][0] + bp[0], acc[i][1] + bp[1],
                             acc[i][2] + bp[2], acc[i][3] + bp[3]);
            o1 = make_float4(acc[i][4] + bp[4], acc[i][5] + bp[5],
                             acc[i][6] + bp[6], acc[i][7] + bp[7]);
        } else {
            o0 = make_float4(acc[i][0], acc[i][1], acc[i][2], acc[i][3]);
            o1 = make_float4(acc[i][4], acc[i][5], acc[i][6], acc[i][7]);
        }
        *(float4*)crow       = o0;
        *(float4*)(crow + 4) = o1;
    }
}

// ---------------------------------------------------------------------------
// Flash attention, fp32. One block = (batch b, head h, 64-query tile).
// 256 threads as 16x16; each thread owns a 4x4 fragment of the 64x64 score
// tile and a 4x4 fragment of the 64x64 output tile. Online softmax with
// row stats reduced over the 16 column-group lanes via shfl.
// Dynamic smem: Qs,Ks,Vs,Ps tiles [64][65] + mask[64] = 66,816 B.
// ---------------------------------------------------------------------------
#define LDP 65
#define ATT_SMEM ((4 * 64 * LDP) * 4 + 64 * 4)

__global__ __launch_bounds__(256, 3)
void flash_attn_kernel(const float* __restrict__ qkv, float* __restrict__ outp) {
    extern __shared__ float sm[];
    float* Qs = sm;                   // [64][65]
    float* Ks = Qs + 64 * LDP;
    float* Vs = Ks + 64 * LDP;
    float* Ps = Vs + 64 * LDP;
    int*   Ms = (int*)(Ps + 64 * LDP);

    const int tid = threadIdx.x;
    const int tm  = tid >> 4;   // row group: rows tm*4 .. tm*4+3
    const int tn  = tid & 15;   // col group: cols tn*4 .. tn*4+3
    const int b   = blockIdx.z;
    const int h   = blockIdx.y;
    const int q0  = blockIdx.x * 64;

    const float* base = qkv + (size_t)b * SEQ * QKV3 + h * HD;

    // Load Q tile (rows = queries, 64 cols of head dim)
    for (int i = tid; i < 64 * 16; i += 256) {
        int r  = i >> 4;
        int c4 = (i & 15) * 4;
        float4 v = *(const float4*)(base + (size_t)(q0 + r) * QKV3 + c4);
        float* q = &Qs[r * LDP + c4];
        q[0] = v.x; q[1] = v.y; q[2] = v.z; q[3] = v.w;
    }

    float m_i[4], l_i[4], o[4][4];
#pragma unroll
    for (int i = 0; i < 4; i++) {
        m_i[i] = -1e30f; l_i[i] = 0.0f;
#pragma unroll
        for (int j = 0; j < 4; j++) o[i][j] = 0.0f;
    }

    const float scale = 0.125f;  // 1/sqrt(64)

    for (int kt = 0; kt < SEQ / 64; kt++) {
        const int k0 = kt * 64;
        // Load K and V tiles
        for (int i = tid; i < 64 * 16; i += 256) {
            int r  = i >> 4;
            int c4 = (i & 15) * 4;
            const float* rp = base + (size_t)(k0 + r) * QKV3 + c4;
            float4 kv = *(const float4*)(rp + HID);
            float4 vv = *(const float4*)(rp + 2 * HID);
            float* ks = &Ks[r * LDP + c4];
            float* vs = &Vs[r * LDP + c4];
            ks[0] = kv.x; ks[1] = kv.y; ks[2] = kv.z; ks[3] = kv.w;
            vs[0] = vv.x; vs[1] = vv.y; vs[2] = vv.z; vs[3] = vv.w;
        }
        if (tid < 64) Ms[tid] = g_mask[b * SEQ + k0 + tid];
        __syncthreads();

        // S = Q @ K^T   (4x4 fragment per thread)
        float s[4][4];
#pragma unroll
        for (int i = 0; i < 4; i++)
#pragma unroll
            for (int j = 0; j < 4; j++) s[i][j] = 0.0f;

#pragma unroll 16
        for (int d = 0; d < 64; d++) {
            float a0 = Qs[(tm * 4 + 0) * LDP + d];
            float a1 = Qs[(tm * 4 + 1) * LDP + d];
            float a2 = Qs[(tm * 4 + 2) * LDP + d];
            float a3 = Qs[(tm * 4 + 3) * LDP + d];
            float b0 = Ks[(tn * 4 + 0) * LDP + d];
            float b1 = Ks[(tn * 4 + 1) * LDP + d];
            float b2 = Ks[(tn * 4 + 2) * LDP + d];
            float b3 = Ks[(tn * 4 + 3) * LDP + d];
            s[0][0] = fmaf(a0, b0, s[0][0]); s[0][1] = fmaf(a0, b1, s[0][1]);
            s[0][2] = fmaf(a0, b2, s[0][2]); s[0][3] = fmaf(a0, b3, s[0][3]);
            s[1][0] = fmaf(a1, b0, s[1][0]); s[1][1] = fmaf(a1, b1, s[1][1]);
            s[1][2] = fmaf(a1, b2, s[1][2]); s[1][3] = fmaf(a1, b3, s[1][3]);
            s[2][0] = fmaf(a2, b0, s[2][0]); s[2][1] = fmaf(a2, b1, s[2][1]);
            s[2][2] = fmaf(a2, b2, s[2][2]); s[2][3] = fmaf(a2, b3, s[2][3]);
            s[3][0] = fmaf(a3, b0, s[3][0]); s[3][1] = fmaf(a3, b1, s[3][1]);
            s[3][2] = fmaf(a3, b2, s[3][2]); s[3][3] = fmaf(a3, b3, s[3][3]);
        }

        // scale + key-padding mask
        int mk[4];
#pragma unroll
        for (int j = 0; j < 4; j++) mk[j] = Ms[tn * 4 + j];
#pragma unroll
        for (int i = 0; i < 4; i++)
#pragma unroll
            for (int j = 0; j < 4; j++)
                s[i][j] = mk[j] ? s[i][j] * scale : -1e30f;

        // online softmax: row max across the 16 column groups
        float mt[4];
#pragma unroll
        for (int i = 0; i < 4; i++) {
            float r = fmaxf(fmaxf(s[i][0], s[i][1]), fmaxf(s[i][2], s[i][3]));
            r = fmaxf(r, __shfl_xor_sync(0xffffffffu, r, 1));
            r = fmaxf(r, __shfl_xor_sync(0xffffffffu, r, 2));
            r = fmaxf(r, __shfl_xor_sync(0xffffffffu, r, 4));
            r = fmaxf(r, __shfl_xor_sync(0xffffffffu, r, 8));
            mt[i] = r;
        }

        float alpha[4];
#pragma unroll
        for (int i = 0; i < 4; i++) {
            float mnew = fmaxf(m_i[i], mt[i]);
            alpha[i] = __expf(m_i[i] - mnew);
            m_i[i] = mnew;
        }

        float p[4][4];
        float lsum[4];
#pragma unroll
        for (int i = 0; i < 4; i++) {
            float r = 0.0f;
#pragma unroll
            for (int j = 0; j < 4; j++) {
                p[i][j] = __expf(s[i][j] - m_i[i]);
                r += p[i][j];
            }
            r += __shfl_xor_sync(0xffffffffu, r, 1);
            r += __shfl_xor_sync(0xffffffffu, r, 2);
            r += __shfl_xor_sync(0xffffffffu, r, 4);
            r += __shfl_xor_sync(0xffffffffu, r, 8);
            lsum[i] = r;
        }

#pragma unroll
        for (int i = 0; i < 4; i++) {
            l_i[i] = l_i[i] * alpha[i] + lsum[i];
#pragma unroll
            for (int j = 0; j < 4; j++) o[i][j] *= alpha[i];
        }

        // stage P in smem for the PV product
#pragma unroll
        for (int i = 0; i < 4; i++) {
            float* pr = &Ps[(tm * 4 + i) * LDP + tn * 4];
            pr[0] = p[i][0]; pr[1] = p[i][1]; pr[2] = p[i][2]; pr[3] = p[i][3];
        }
        __syncthreads();

        // O += P @ V
#pragma unroll 16
        for (int k = 0; k < 64; k++) {
            float pa0 = Ps[(tm * 4 + 0) * LDP + k];
            float pa1 = Ps[(tm * 4 + 1) * LDP + k];
            float pa2 = Ps[(tm * 4 + 2) * LDP + k];
            float pa3 = Ps[(tm * 4 + 3) * LDP + k];
            float v0 = Vs[k * LDP + tn * 4 + 0];
            float v1 = Vs[k * LDP + tn * 4 + 1];
            float v2 = Vs[k * LDP + tn * 4 + 2];
            float v3 = Vs[k * LDP + tn * 4 + 3];
            o[0][0] = fmaf(pa0, v0, o[0][0]); o[0][1] = fmaf(pa0, v1, o[0][1]);
            o[0][2] = fmaf(pa0, v2, o[0][2]); o[0][3] = fmaf(pa0, v3, o[0][3]);
            o[1][0] = fmaf(pa1, v0, o[1][0]); o[1][1] = fmaf(pa1, v1, o[1][1]);
            o[1][2] = fmaf(pa1, v2, o[1][2]); o[1][3] = fmaf(pa1, v3, o[1][3]);
            o[2][0] = fmaf(pa2, v0, o[2][0]); o[2][1] = fmaf(pa2, v1, o[2][1]);
            o[2][2] = fmaf(pa2, v2, o[2][2]); o[2][3] = fmaf(pa2, v3, o[2][3]);
            o[3][0] = fmaf(pa3, v0, o[3][0]); o[3][1] = fmaf(pa3, v1, o[3][1]);
            o[3][2] = fmaf(pa3, v2, o[3][2]); o[3][3] = fmaf(pa3, v3, o[3][3]);
        }
        __syncthreads();
    }

    // epilogue: normalize and write [b,s,h*64+d]
#pragma unroll
    for (int i = 0; i < 4; i++) {
        float inv = 1.0f / l_i[i];
        float* op = outp + (size_t)(b * SEQ + q0 + tm * 4 + i) * HID + h * HD + tn * 4;
        float4 v = make_float4(o[i][0] * inv, o[i][1] * inv, o[i][2] * inv, o[i][3] * inv);
        *(float4*)op = v;
    }
}

// ---------------------------------------------------------------------------
// Launch
// ---------------------------------------------------------------------------
extern "C" void kernel_launch(void* const* d_in, const int* in_sizes, int n_in,
                              void* d_out, int out_size) {
    const float* hidden = (const float*)d_in[0];
    const void*  maskp  = d_in[1];
    const float* Wqkv   = (const float*)d_in[2];
    const float* Wout   = (const float*)d_in[3];
    const float* bout   = (const float*)d_in[4];
    float*       out    = (float*)d_out;

    void *p_qkv, *p_att;
    cudaGetSymbolAddress(&p_qkv, g_qkv);
    cudaGetSymbolAddress(&p_att, g_att);

    // 1. canonicalize mask
    mask_convert_kernel<<<1, 256>>>(maskp, BATCH * SEQ);

    // 2. QKV projection: [8192,1024] @ [1024,3072]
    sgemm128_kernel<false><<<dim3(QKV3 / 128, (BATCH * SEQ) / 128), 256>>>(
        hidden, Wqkv, nullptr, (float*)p_qkv, BATCH * SEQ, QKV3, HID);

    // 3. flash attention
    cudaFuncSetAttribute(flash_attn_kernel,
                         cudaFuncAttributeMaxDynamicSharedMemorySize, ATT_SMEM);
    flash_attn_kernel<<<dim3(SEQ / 64, NH, BATCH), 256, ATT_SMEM>>>(
        (const float*)p_qkv, (float*)p_att);

    // 4. output projection + bias: [8192,1024] @ [1024,1024] + bout
    sgemm128_kernel<true><<<dim3(HID / 128, (BATCH * SEQ) / 128), 256>>>(
        (const float*)p_att, Wout, bout, out, BATCH * SEQ, HID, HID);
}

// round 3
// speedup vs baseline: 1.4223x; 1.4223x over previous
#include <cuda_runtime.h>
#include <cuda_bf16.h>
#include <cstdint>

#define BATCH 4
#define SEQ   2048
#define NH    16
#define HD    64
#define HID   1024
#define QKV3  3072
#define MROWS (BATCH * SEQ)        // 8192

// ---------------------------------------------------------------------------
// Scratch (static device globals — allocation-free per harness rules)
// ---------------------------------------------------------------------------
__device__ float         g_qkv[MROWS * QKV3];          // 96 MB fp32 qkv
__device__ float         g_att[MROWS * HID];           // 32 MB attention out
__device__ int           g_mask[BATCH * SEQ];
__device__ int           g_tileflag[BATCH * (SEQ / 64)];
__device__ __nv_bfloat16 g_sh[MROWS * HID];            // activation split hi
__device__ __nv_bfloat16 g_sl[MROWS * HID];            // activation split lo
__device__ __nv_bfloat16 g_wh[(QKV3 + HID) * HID];     // W^T hi: Wqkv^T rows 0..3071, Wout^T rows 3072..4095
__device__ __nv_bfloat16 g_wl[(QKV3 + HID) * HID];     // W^T lo

// ---------------------------------------------------------------------------
// PTX helpers (arch-portable: sm_80+ instructions only)
// ---------------------------------------------------------------------------
__device__ __forceinline__ uint32_t smem_u32(const void* p) {
    uint32_t a;
    asm("{ .reg .u64 t; cvta.to.shared.u64 t, %1; cvt.u32.u64 %0, t; }" : "=r"(a) : "l"(p));
    return a;
}
__device__ __forceinline__ void ldsm_x4(uint32_t& r0, uint32_t& r1, uint32_t& r2, uint32_t& r3,
                                        uint32_t addr) {
    asm volatile("ldmatrix.sync.aligned.m8n8.x4.shared.b16 {%0,%1,%2,%3}, [%4];"
                 : "=r"(r0), "=r"(r1), "=r"(r2), "=r"(r3) : "r"(addr));
}
__device__ __forceinline__ void mma_bf16(float* c, const uint32_t* a, uint32_t b0, uint32_t b1) {
    asm volatile(
        "mma.sync.aligned.m16n8k16.row.col.f32.bf16.bf16.f32 "
        "{%0,%1,%2,%3}, {%4,%5,%6,%7}, {%8,%9}, {%0,%1,%2,%3};"
        : "+f"(c[0]), "+f"(c[1]), "+f"(c[2]), "+f"(c[3])
        : "r"(a[0]), "r"(a[1]), "r"(a[2]), "r"(a[3]), "r"(b0), "r"(b1));
}
#define CP_ASYNC16(dst, src) \
    asm volatile("cp.async.cg.shared.global [%0], [%1], 16;" :: "r"(dst), "l"(src))
#define CP_COMMIT() asm volatile("cp.async.commit_group;" ::: "memory")
#define CP_WAIT(n)  asm volatile("cp.async.wait_group %0;" :: "n"(n) : "memory")

// ---------------------------------------------------------------------------
// Mask canonicalizer + per-64-tile attend flags
// ---------------------------------------------------------------------------
__global__ void mask_convert_kernel(const void* __restrict__ raw, int n) {
    __shared__ int mode;
    if (threadIdx.x == 0) {
        unsigned w0 = ((const unsigned*)raw)[0];
        if (w0 == 1u || w0 == 0u)    mode = 0;  // int32
        else if (w0 == 0x3F800000u)  mode = 1;  // float32
        else if (w0 == 0x01010101u)  mode = 2;  // uint8
        else if (w0 == 0x3F803F80u)  mode = 3;  // bf16 pair
        else                          mode = 2;
    }
    __syncthreads();
    int m = mode;
    for (int i = threadIdx.x; i < n; i += blockDim.x) {
        int v;
        if (m == 0)      v = (((const int*)raw)[i] != 0);
        else if (m == 1) v = (((const float*)raw)[i] != 0.0f);
        else if (m == 2) v = (((const unsigned char*)raw)[i] != 0);
        else { unsigned short h = ((const unsigned short*)raw)[i]; v = ((h & 0x7FFF) != 0); }
        g_mask[i] = v;
    }
    __syncthreads();
    for (int t = threadIdx.x; t < BATCH * (SEQ / 64); t += blockDim.x) {
        int b = t / (SEQ / 64), tt = t % (SEQ / 64);
        int f = 0;
        for (int j = 0; j < 64; j++) f |= g_mask[b * SEQ + tt * 64 + j];
        g_tileflag[t] = f;
    }
}

// ---------------------------------------------------------------------------
// bf16 split kernels
// ---------------------------------------------------------------------------
__global__ void splitA_kernel(const float* __restrict__ A,
                              __nv_bfloat16* __restrict__ Ah,
                              __nv_bfloat16* __restrict__ Al, int n4) {
    int stride = gridDim.x * blockDim.x;
    for (int i = blockIdx.x * blockDim.x + threadIdx.x; i < n4; i += stride) {
        float4 v = ((const float4*)A)[i];
        __nv_bfloat16 h0 = __float2bfloat16(v.x), h1 = __float2bfloat16(v.y);
        __nv_bfloat16 h2 = __float2bfloat16(v.z), h3 = __float2bfloat16(v.w);
        __nv_bfloat16 l0 = __float2bfloat16(v.x - __bfloat162float(h0));
        __nv_bfloat16 l1 = __float2bfloat16(v.y - __bfloat162float(h1));
        __nv_bfloat16 l2 = __float2bfloat16(v.z - __bfloat162float(h2));
        __nv_bfloat16 l3 = __float2bfloat16(v.w - __bfloat162float(h3));
        __nv_bfloat162 hp0 = {h0, h1}, hp1 = {h2, h3}, lp0 = {l0, l1}, lp1 = {l2, l3};
        ((__nv_bfloat162*)Ah)[i * 2]     = hp0;
        ((__nv_bfloat162*)Ah)[i * 2 + 1] = hp1;
        ((__nv_bfloat162*)Al)[i * 2]     = lp0;
        ((__nv_bfloat162*)Al)[i * 2 + 1] = lp1;
    }
}

// B [K,N] fp32 -> B^T [N,K] bf16 hi/lo
__global__ void splitBT_kernel(const float* __restrict__ B,
                               __nv_bfloat16* __restrict__ BTh,
                               __nv_bfloat16* __restrict__ BTl, int K, int N) {
    __shared__ float tile[32][33];
    int k0 = blockIdx.y * 32, n0 = blockIdx.x * 32;
    int tx = threadIdx.x & 31, ty = threadIdx.x >> 5;
    for (int r = ty; r < 32; r += 8)
        tile[r][tx] = B[(size_t)(k0 + r) * N + n0 + tx];
    __syncthreads();
    for (int r = ty; r < 32; r += 8) {
        float v = tile[tx][r];
        __nv_bfloat16 h = __float2bfloat16(v);
        __nv_bfloat16 l = __float2bfloat16(v - __bfloat162float(h));
        size_t o = (size_t)(n0 + r) * K + k0 + tx;
        BTh[o] = h;
        BTl[o] = l;
    }
}

// ---------------------------------------------------------------------------
// mma.sync bf16x3 GEMM: C[M,N] = A[M,K] @ BT[N,K]^T (+bias)
// CTA 128x128, 8 warps (4M x 2N), each warp 32x64. K chunks of 32,
// 3-stage cp.async pipeline. smem tiles padded to 80B rows (conflict-free).
// ---------------------------------------------------------------------------
#define KC        32
#define STAGES    3
#define TROW      80                      // bytes per smem tile row (32 bf16 + pad)
#define TILE_B    (128 * TROW)            // 10240
#define STAGE_B   (4 * TILE_B)            // 40960: Ah | Al | Bh | Bl
#define TC_SMEM   (STAGES * STAGE_B)      // 122880

template <bool BIAS>
__global__ __launch_bounds__(256, 1)
void mma_gemm_kernel(const __nv_bfloat16* __restrict__ Ah, const __nv_bfloat16* __restrict__ Al,
                     const __nv_bfloat16* __restrict__ BTh, const __nv_bfloat16* __restrict__ BTl,
                     const float* __restrict__ bias, float* __restrict__ C,
                     int M, int N, int K) {
    extern __shared__ char smem[];
    const uint32_t sb = smem_u32(smem);
    const int tid   = threadIdx.x;
    const int lane  = tid & 31;
    const int wid   = tid >> 5;
    const int warpM = wid & 3;            // 4 warps in M
    const int warpN = wid >> 2;           // 2 warps in N
    const int m0 = blockIdx.y * 128;
    const int n0 = blockIdx.x * 128;
    const int nch = K / KC;

    // global->smem loader: 8 x 16B per thread per stage
    auto load_stage = [&](int kc0, int s) {
        const uint32_t stg = sb + s * STAGE_B;
#pragma unroll
        for (int t = 0; t < 8; t++) {
            const int tile = t >> 1;                       // 0:Ah 1:Al 2:Bh 3:Bl
            const int rem  = tid + (t & 1) * 256;          // 0..511
            const int row  = rem >> 2;
            const int q    = rem & 3;
            const __nv_bfloat16* src;
            if (tile == 0)      src = Ah  + (size_t)(m0 + row) * K + kc0 + q * 8;
            else if (tile == 1) src = Al  + (size_t)(m0 + row) * K + kc0 + q * 8;
            else if (tile == 2) src = BTh + (size_t)(n0 + row) * K + kc0 + q * 8;
            else                src = BTl + (size_t)(n0 + row) * K + kc0 + q * 8;
            CP_ASYNC16(stg + tile * TILE_B + row * TROW + q * 16, src);
        }
        CP_COMMIT();
    };

    float c[2][8][4];
#pragma unroll
    for (int i = 0; i < 2; i++)
#pragma unroll
        for (int j = 0; j < 8; j++)
#pragma unroll
            for (int r = 0; r < 4; r++) c[i][j][r] = 0.0f;

    // ldmatrix per-lane address components
    const int arow = warpM * 32 + (lane & 15);             // + mt*16
    const int acol = (lane >> 4) * 8;                      // k sub-half
    const int brow = warpN * 64 + (lane & 7) + ((lane >> 4) << 3);  // + np*16
    const int bck  = ((lane >> 3) & 1) * 8;                // k sub-half

    // prologue
    load_stage(0, 0);
    load_stage(KC, 1);

    for (int ch = 0; ch < nch; ch++) {
        CP_WAIT(STAGES - 2);
        __syncthreads();
        if (ch + STAGES - 1 < nch) load_stage((ch + STAGES - 1) * KC, (ch + STAGES - 1) % STAGES);
        else CP_COMMIT();

        const uint32_t stg = sb + (ch % STAGES) * STAGE_B;
        const uint32_t ahb = stg;
        const uint32_t alb = stg + TILE_B;
        const uint32_t bhb = stg + 2 * TILE_B;
        const uint32_t blb = stg + 3 * TILE_B;

#pragma unroll
        for (int k16 = 0; k16 < 2; k16++) {
            uint32_t fah[2][4], fal[2][4];
#pragma unroll
            for (int mt = 0; mt < 2; mt++) {
                uint32_t off = (uint32_t)(arow + mt * 16) * TROW + (k16 * 16 + acol) * 2;
                ldsm_x4(fah[mt][0], fah[mt][1], fah[mt][2], fah[mt][3], ahb + off);
                ldsm_x4(fal[mt][0], fal[mt][1], fal[mt][2], fal[mt][3], alb + off);
            }
            uint32_t fbh[4][4], fbl[4][4];
#pragma unroll
            for (int np = 0; np < 4; np++) {
                uint32_t off = (uint32_t)(brow + np * 16) * TROW + (k16 * 16 + bck) * 2;
                ldsm_x4(fbh[np][0], fbh[np][1], fbh[np][2], fbh[np][3], bhb + off);
                ldsm_x4(fbl[np][0], fbl[np][1], fbl[np][2], fbl[np][3], blb + off);
            }
#pragma unroll
            for (int mt = 0; mt < 2; mt++)
#pragma unroll
                for (int nt = 0; nt < 8; nt++) {
                    const uint32_t bh0 = fbh[nt >> 1][(nt & 1) * 2];
                    const uint32_t bh1 = fbh[nt >> 1][(nt & 1) * 2 + 1];
                    const uint32_t bl0 = fbl[nt >> 1][(nt & 1) * 2];
                    const uint32_t bl1 = fbl[nt >> 1][(nt & 1) * 2 + 1];
                    mma_bf16(c[mt][nt], fah[mt], bh0, bh1);   // hi*hi
                    mma_bf16(c[mt][nt], fah[mt], bl0, bl1);   // hi*lo
                    mma_bf16(c[mt][nt], fal[mt], bh0, bh1);   // lo*hi
                }
        }
        __syncthreads();
    }

    // epilogue
    const int g   = lane >> 2;
    const int tig = lane & 3;
#pragma unroll
    for (int mt = 0; mt < 2; mt++) {
        const int row = m0 + warpM * 32 + mt * 16 + g;
#pragma unroll
        for (int nt = 0; nt < 8; nt++) {
            const int col = n0 + warpN * 64 + nt * 8 + tig * 2;
            float2 v0 = make_float2(c[mt][nt][0], c[mt][nt][1]);
            float2 v1 = make_float2(c[mt][nt][2], c[mt][nt][3]);
            if (BIAS) {
                v0.x += bias[col];     v0.y += bias[col + 1];
                v1.x += bias[col];     v1.y += bias[col + 1];
            }
            *(float2*)(C + (size_t)row * N + col)       = v0;
            *(float2*)(C + (size_t)(row + 8) * N + col) = v1;
        }
    }
}

// ---------------------------------------------------------------------------
// Flash attention, fp32 + fully-masked-tile skipping. (R1-proven core.)
// ---------------------------------------------------------------------------
#define LDP 65
#define ATT_SMEM ((4 * 64 * LDP) * 4 + 64 * 4)

__global__ __launch_bounds__(256, 3)
void flash_attn_kernel(const float* __restrict__ qkv, float* __restrict__ outp) {
    extern __shared__ float sm[];
    float* Qs = sm;
    float* Ks = Qs + 64 * LDP;
    float* Vs = Ks + 64 * LDP;
    float* Ps = Vs + 64 * LDP;
    int*   Ms = (int*)(Ps + 64 * LDP);

    const int tid = threadIdx.x;
    const int tm  = tid >> 4;
    const int tn  = tid & 15;
    const int b   = blockIdx.z;
    const int h   = blockIdx.y;
    const int q0  = blockIdx.x * 64;

    const float* base = qkv + (size_t)b * SEQ * QKV3 + h * HD;

    for (int i = tid; i < 64 * 16; i += 256) {
        int r = i >> 4, c4 = (i & 15) * 4;
        float4 v = *(const float4*)(base + (size_t)(q0 + r) * QKV3 + c4);
        float* q = &Qs[r * LDP + c4];
        q[0] = v.x; q[1] = v.y; q[2] = v.z; q[3] = v.w;
    }

    float m_i[4], l_i[4], o[4][4];
#pragma unroll
    for (int i = 0; i < 4; i++) {
        m_i[i] = -1e30f; l_i[i] = 0.0f;
#pragma unroll
        for (int j = 0; j < 4; j++) o[i][j] = 0.0f;
    }
    const float scale = 0.125f;

    for (int kt = 0; kt < SEQ / 64; kt++) {
        if (!g_tileflag[b * (SEQ / 64) + kt]) continue;
        const int k0 = kt * 64;
        for (int i = tid; i < 64 * 16; i += 256) {
            int r = i >> 4, c4 = (i & 15) * 4;
            const float* rp = base + (size_t)(k0 + r) * QKV3 + c4;
            float4 kv = *(const float4*)(rp + HID);
            float4 vv = *(const float4*)(rp + 2 * HID);
            float* ks = &Ks[r * LDP + c4];
            float* vs = &Vs[r * LDP + c4];
            ks[0] = kv.x; ks[1] = kv.y; ks[2] = kv.z; ks[3] = kv.w;
            vs[0] = vv.x; vs[1] = vv.y; vs[2] = vv.z; vs[3] = vv.w;
        }
        if (tid < 64) Ms[tid] = g_mask[b * SEQ + k0 + tid];
        __syncthreads();

        float s[4][4];
#pragma unroll
        for (int i = 0; i < 4; i++)
#pragma unroll
            for (int j = 0; j < 4; j++) s[i][j] = 0.0f;

#pragma unroll 16
        for (int d = 0; d < 64; d++) {
            float a0 = Qs[(tm * 4 + 0) * LDP + d];
            float a1 = Qs[(tm * 4 + 1) * LDP + d];
            float a2 = Qs[(tm * 4 + 2) * LDP + d];
            float a3 = Qs[(tm * 4 + 3) * LDP + d];
            float b0 = Ks[(tn * 4 + 0) * LDP + d];
            float b1 = Ks[(tn * 4 + 1) * LDP + d];
            float b2 = Ks[(tn * 4 + 2) * LDP + d];
            float b3 = Ks[(tn * 4 + 3) * LDP + d];
            s[0][0] = fmaf(a0, b0, s[0][0]); s[0][1] = fmaf(a0, b1, s[0][1]);
            s[0][2] = fmaf(a0, b2, s[0][2]); s[0][3] = fmaf(a0, b3, s[0][3]);
            s[1][0] = fmaf(a1, b0, s[1][0]); s[1][1] = fmaf(a1, b1, s[1][1]);
            s[1][2] = fmaf(a1, b2, s[1][2]); s[1][3] = fmaf(a1, b3, s[1][3]);
            s[2][0] = fmaf(a2, b0, s[2][0]); s[2][1] = fmaf(a2, b1, s[2][1]);
            s[2][2] = fmaf(a2, b2, s[2][2]); s[2][3] = fmaf(a2, b3, s[2][3]);
            s[3][0] = fmaf(a3, b0, s[3][0]); s[3][1] = fmaf(a3, b1, s[3][1]);
            s[3][2] = fmaf(a3, b2, s[3][2]); s[3][3] = fmaf(a3, b3, s[3][3]);
        }

        int mk[4];
#pragma unroll
        for (int j = 0; j < 4; j++) mk[j] = Ms[tn * 4 + j];
#pragma unroll
        for (int i = 0; i < 4; i++)
#pragma unroll
            for (int j = 0; j < 4; j++)
                s[i][j] = mk[j] ? s[i][j] * scale : -1e30f;

        float mt[4];
#pragma unroll
        for (int i = 0; i < 4; i++) {
            float r = fmaxf(fmaxf(s[i][0], s[i][1]), fmaxf(s[i][2], s[i][3]));
            r = fmaxf(r, __shfl_xor_sync(0xffffffffu, r, 1));
            r = fmaxf(r, __shfl_xor_sync(0xffffffffu, r, 2));
            r = fmaxf(r, __shfl_xor_sync(0xffffffffu, r, 4));
            r = fmaxf(r, __shfl_xor_sync(0xffffffffu, r, 8));
            mt[i] = r;
        }

        float alpha[4];
#pragma unroll
        for (int i = 0; i < 4; i++) {
            float mnew = fmaxf(m_i[i], mt[i]);
            alpha[i] = __expf(m_i[i] - mnew);
            m_i[i] = mnew;
        }

        float p[4][4], lsum[4];
#pragma unroll
        for (int i = 0; i < 4; i++) {
            float r = 0.0f;
#pragma unroll
            for (int j = 0; j < 4; j++) {
                p[i][j] = __expf(s[i][j] - m_i[i]);
                r += p[i][j];
            }
            r += __shfl_xor_sync(0xffffffffu, r, 1);
            r += __shfl_xor_sync(0xffffffffu, r, 2);
            r += __shfl_xor_sync(0xffffffffu, r, 4);
            r += __shfl_xor_sync(0xffffffffu, r, 8);
            lsum[i] = r;
        }

#pragma unroll
        for (int i = 0; i < 4; i++) {
            l_i[i] = l_i[i] * alpha[i] + lsum[i];
#pragma unroll
            for (int j = 0; j < 4; j++) o[i][j] *= alpha[i];
        }

#pragma unroll
        for (int i = 0; i < 4; i++) {
            float* pr = &Ps[(tm * 4 + i) * LDP + tn * 4];
            pr[0] = p[i][0]; pr[1] = p[i][1]; pr[2] = p[i][2]; pr[3] = p[i][3];
        }
        __syncthreads();

#pragma unroll 16
        for (int k = 0; k < 64; k++) {
            float pa0 = Ps[(tm * 4 + 0) * LDP + k];
            float pa1 = Ps[(tm * 4 + 1) * LDP + k];
            float pa2 = Ps[(tm * 4 + 2) * LDP + k];
            float pa3 = Ps[(tm * 4 + 3) * LDP + k];
            float v0 = Vs[k * LDP + tn * 4 + 0];
            float v1 = Vs[k * LDP + tn * 4 + 1];
            float v2 = Vs[k * LDP + tn * 4 + 2];
            float v3 = Vs[k * LDP + tn * 4 + 3];
            o[0][0] = fmaf(pa0, v0, o[0][0]); o[0][1] = fmaf(pa0, v1, o[0][1]);
            o[0][2] = fmaf(pa0, v2, o[0][2]); o[0][3] = fmaf(pa0, v3, o[0][3]);
            o[1][0] = fmaf(pa1, v0, o[1][0]); o[1][1] = fmaf(pa1, v1, o[1][1]);
            o[1][2] = fmaf(pa1, v2, o[1][2]); o[1][3] = fmaf(pa1, v3, o[1][3]);
            o[2][0] = fmaf(pa2, v0, o[2][0]); o[2][1] = fmaf(pa2, v1, o[2][1]);
            o[2][2] = fmaf(pa2, v2, o[2][2]); o[2][3] = fmaf(pa2, v3, o[2][3]);
            o[3][0] = fmaf(pa3, v0, o[3][0]); o[3][1] = fmaf(pa3, v1, o[3][1]);
            o[3][2] = fmaf(pa3, v2, o[3][2]); o[3][3] = fmaf(pa3, v3, o[3][3]);
        }
        __syncthreads();
    }

#pragma unroll
    for (int i = 0; i < 4; i++) {
        float inv = 1.0f / l_i[i];
        float* op = outp + (size_t)(b * SEQ + q0 + tm * 4 + i) * HID + h * HD + tn * 4;
        float4 v = make_float4(o[i][0] * inv, o[i][1] * inv, o[i][2] * inv, o[i][3] * inv);
        *(float4*)op = v;
    }
}

// ---------------------------------------------------------------------------
// Launch
// ---------------------------------------------------------------------------
extern "C" void kernel_launch(void* const* d_in, const int* in_sizes, int n_in,
                              void* d_out, int out_size) {
    const float* hidden = (const float*)d_in[0];
    const void*  maskp  = d_in[1];
    const float* Wqkv   = (const float*)d_in[2];
    const float* Wout   = (const float*)d_in[3];
    const float* bout   = (const float*)d_in[4];
    float*       out    = (float*)d_out;

    void *p_qkv, *p_att, *p_sh, *p_sl, *p_wh, *p_wl;
    cudaGetSymbolAddress(&p_qkv, g_qkv);
    cudaGetSymbolAddress(&p_att, g_att);
    cudaGetSymbolAddress(&p_sh, g_sh);
    cudaGetSymbolAddress(&p_sl, g_sl);
    cudaGetSymbolAddress(&p_wh, g_wh);
    cudaGetSymbolAddress(&p_wl, g_wl);

    cudaFuncSetAttribute(flash_attn_kernel,
                         cudaFuncAttributeMaxDynamicSharedMemorySize, ATT_SMEM);
    cudaFuncSetAttribute(mma_gemm_kernel<false>,
                         cudaFuncAttributeMaxDynamicSharedMemorySize, TC_SMEM);
    cudaFuncSetAttribute(mma_gemm_kernel<true>,
                         cudaFuncAttributeMaxDynamicSharedMemorySize, TC_SMEM);

    // 1. mask canonicalize + tile flags
    mask_convert_kernel<<<1, 256>>>(maskp, BATCH * SEQ);

    // 2. split inputs to bf16 hi/lo
    splitA_kernel<<<592, 256>>>(hidden, (__nv_bfloat16*)p_sh, (__nv_bfloat16*)p_sl,
                                MROWS * HID / 4);
    splitBT_kernel<<<dim3(QKV3 / 32, HID / 32), 256>>>(
        Wqkv, (__nv_bfloat16*)p_wh, (__nv_bfloat16*)p_wl, HID, QKV3);
    splitBT_kernel<<<dim3(HID / 32, HID / 32), 256>>>(
        Wout, (__nv_bfloat16*)p_wh + (size_t)QKV3 * HID,
        (__nv_bfloat16*)p_wl + (size_t)QKV3 * HID, HID, HID);

    // 3. QKV projection (mma.sync bf16x3): [8192,1024] @ [1024,3072]
    mma_gemm_kernel<false><<<dim3(QKV3 / 128, MROWS / 128), 256, TC_SMEM>>>(
        (const __nv_bfloat16*)p_sh, (const __nv_bfloat16*)p_sl,
        (const __nv_bfloat16*)p_wh, (const __nv_bfloat16*)p_wl,
        nullptr, (float*)p_qkv, MROWS, QKV3, HID);

    // 4. flash attention (fp32, masked-tile skipping)
    flash_attn_kernel<<<dim3(SEQ / 64, NH, BATCH), 256, ATT_SMEM>>>(
        (const float*)p_qkv, (float*)p_att);

    // 5. split attention output
    splitA_kernel<<<592, 256>>>((const float*)p_att, (__nv_bfloat16*)p_sh,
                                (__nv_bfloat16*)p_sl, MROWS * HID / 4);

    // 6. output projection (mma.sync bf16x3, +bias): [8192,1024] @ [1024,1024]
    mma_gemm_kernel<true><<<dim3(HID / 128, MROWS / 128), 256, TC_SMEM>>>(
        (const __nv_bfloat16*)p_sh, (const __nv_bfloat16*)p_sl,
        (const __nv_bfloat16*)p_wh + (size_t)QKV3 * HID,
        (const __nv_bfloat16*)p_wl + (size_t)QKV3 * HID,
        bout, out, MROWS, HID, HID);
}

// round 4
// speedup vs baseline: 2.8826x; 2.0267x over previous
#include <cuda_runtime.h>
#include <cuda_bf16.h>
#include <cstdint>

#define BATCH 4
#define SEQ   2048
#define NH    16
#define HD    64
#define HID   1024
#define QKV3  3072
#define MROWS (BATCH * SEQ)        // 8192

// 0.125 * log2(e): folded into Q at the QKV epilogue (softmax in base-2 domain)
#define QSF 0.18033688011112042f

// ---------------------------------------------------------------------------
// Scratch (static device globals — allocation-free per harness rules)
// ---------------------------------------------------------------------------
__device__ __nv_bfloat16 g_qh[MROWS * QKV3];           // qkv hi split (48 MB)
__device__ __nv_bfloat16 g_ql[MROWS * QKV3];           // qkv lo split
__device__ int           g_mask[BATCH * SEQ];
__device__ unsigned long long g_mbits[BATCH * 32];     // 64-key tile bitmasks
__device__ __nv_bfloat16 g_sh[MROWS * HID];            // activation hi (hidden, then attn out)
__device__ __nv_bfloat16 g_sl[MROWS * HID];            // activation lo
__device__ __nv_bfloat16 g_wh[(QKV3 + HID) * HID];     // W^T hi
__device__ __nv_bfloat16 g_wl[(QKV3 + HID) * HID];     // W^T lo

// ---------------------------------------------------------------------------
// PTX helpers (arch-portable: sm_80+ only; tcgen05 is NOT available through
// the harness's compute_103 virtual arch)
// ---------------------------------------------------------------------------
__device__ __forceinline__ uint32_t smem_u32(const void* p) {
    uint32_t a;
    asm("{ .reg .u64 t; cvta.to.shared.u64 t, %1; cvt.u32.u64 %0, t; }" : "=r"(a) : "l"(p));
    return a;
}
__device__ __forceinline__ void ldsm_x4(uint32_t& r0, uint32_t& r1, uint32_t& r2, uint32_t& r3,
                                        uint32_t addr) {
    asm volatile("ldmatrix.sync.aligned.m8n8.x4.shared.b16 {%0,%1,%2,%3}, [%4];"
                 : "=r"(r0), "=r"(r1), "=r"(r2), "=r"(r3) : "r"(addr));
}
__device__ __forceinline__ void ldsm_x4t(uint32_t& r0, uint32_t& r1, uint32_t& r2, uint32_t& r3,
                                         uint32_t addr) {
    asm volatile("ldmatrix.sync.aligned.m8n8.x4.trans.shared.b16 {%0,%1,%2,%3}, [%4];"
                 : "=r"(r0), "=r"(r1), "=r"(r2), "=r"(r3) : "r"(addr));
}
__device__ __forceinline__ void mma_bf16(float* c, const uint32_t* a, uint32_t b0, uint32_t b1) {
    asm volatile(
        "mma.sync.aligned.m16n8k16.row.col.f32.bf16.bf16.f32 "
        "{%0,%1,%2,%3}, {%4,%5,%6,%7}, {%8,%9}, {%0,%1,%2,%3};"
        : "+f"(c[0]), "+f"(c[1]), "+f"(c[2]), "+f"(c[3])
        : "r"(a[0]), "r"(a[1]), "r"(a[2]), "r"(a[3]), "r"(b0), "r"(b1));
}
__device__ __forceinline__ float fexp2(float x) {
    float y; asm("ex2.approx.f32 %0, %1;" : "=f"(y) : "f"(x)); return y;
}
__device__ __forceinline__ void split_pack(float x, float y, uint32_t& hp, uint32_t& lp) {
    __nv_bfloat162 hv, lv;
    hv.x = __float2bfloat16(x);
    hv.y = __float2bfloat16(y);
    lv.x = __float2bfloat16(x - __bfloat162float(hv.x));
    lv.y = __float2bfloat16(y - __bfloat162float(hv.y));
    hp = *(uint32_t*)&hv;
    lp = *(uint32_t*)&lv;
}
#define CP_ASYNC16(dst, src) \
    asm volatile("cp.async.cg.shared.global [%0], [%1], 16;" :: "r"(dst), "l"(src))
#define CP_COMMIT() asm volatile("cp.async.commit_group;" ::: "memory")
#define CP_WAIT(n)  asm volatile("cp.async.wait_group %0;" :: "n"(n) : "memory")

// ---------------------------------------------------------------------------
// Mask canonicalizer + per-64-key-tile bitmasks
// ---------------------------------------------------------------------------
__global__ void mask_convert_kernel(const void* __restrict__ raw, int n) {
    __shared__ int mode;
    if (threadIdx.x == 0) {
        unsigned w0 = ((const unsigned*)raw)[0];
        if (w0 == 1u || w0 == 0u)    mode = 0;  // int32
        else if (w0 == 0x3F800000u)  mode = 1;  // float32
        else if (w0 == 0x01010101u)  mode = 2;  // uint8
        else if (w0 == 0x3F803F80u)  mode = 3;  // bf16 pair
        else                          mode = 2;
    }
    __syncthreads();
    int m = mode;
    for (int i = threadIdx.x; i < n; i += blockDim.x) {
        int v;
        if (m == 0)      v = (((const int*)raw)[i] != 0);
        else if (m == 1) v = (((const float*)raw)[i] != 0.0f);
        else if (m == 2) v = (((const unsigned char*)raw)[i] != 0);
        else { unsigned short h = ((const unsigned short*)raw)[i]; v = ((h & 0x7FFF) != 0); }
        g_mask[i] = v;
    }
    __syncthreads();
    for (int t = threadIdx.x; t < BATCH * 32; t += blockDim.x) {
        int b = t >> 5, kt = t & 31;
        unsigned long long mb = 0ull;
        for (int j = 0; j < 64; j++)
            mb |= ((unsigned long long)(g_mask[b * SEQ + kt * 64 + j] & 1)) << j;
        g_mbits[t] = mb;
    }
}

// ---------------------------------------------------------------------------
// bf16 split kernels (hidden input + weights)
// ---------------------------------------------------------------------------
__global__ void splitA_kernel(const float* __restrict__ A,
                              __nv_bfloat16* __restrict__ Ah,
                              __nv_bfloat16* __restrict__ Al, int n4) {
    int stride = gridDim.x * blockDim.x;
    for (int i = blockIdx.x * blockDim.x + threadIdx.x; i < n4; i += stride) {
        float4 v = ((const float4*)A)[i];
        uint32_t h0, l0, h1, l1;
        split_pack(v.x, v.y, h0, l0);
        split_pack(v.z, v.w, h1, l1);
        ((uint32_t*)Ah)[i * 2]     = h0;
        ((uint32_t*)Ah)[i * 2 + 1] = h1;
        ((uint32_t*)Al)[i * 2]     = l0;
        ((uint32_t*)Al)[i * 2 + 1] = l1;
    }
}

// B [K,N] fp32 -> B^T [N,K] bf16 hi/lo
__global__ void splitBT_kernel(const float* __restrict__ B,
                               __nv_bfloat16* __restrict__ BTh,
                               __nv_bfloat16* __restrict__ BTl, int K, int N) {
    __shared__ float tile[32][33];
    int k0 = blockIdx.y * 32, n0 = blockIdx.x * 32;
    int tx = threadIdx.x & 31, ty = threadIdx.x >> 5;
    for (int r = ty; r < 32; r += 8)
        tile[r][tx] = B[(size_t)(k0 + r) * N + n0 + tx];
    __syncthreads();
    for (int r = ty; r < 32; r += 8) {
        float v = tile[tx][r];
        __nv_bfloat16 h = __float2bfloat16(v);
        __nv_bfloat16 l = __float2bfloat16(v - __bfloat162float(h));
        size_t o = (size_t)(n0 + r) * K + k0 + tx;
        BTh[o] = h;
        BTl[o] = l;
    }
}

// ---------------------------------------------------------------------------
// mma.sync bf16x3 GEMM (R3-proven core). MODE 0: bf16 hi/lo output + Q-scale
// on cols < HID (QKV projection). MODE 1: fp32 output + bias (out-proj).
// ---------------------------------------------------------------------------
#define KC        32
#define STAGES    3
#define TROW      80
#define TILE_B    (128 * TROW)
#define STAGE_B   (4 * TILE_B)
#define TC_SMEM   (STAGES * STAGE_B)   // 122880

template <int MODE>
__global__ __launch_bounds__(256, 1)
void mma_gemm_kernel(const __nv_bfloat16* __restrict__ Ah, const __nv_bfloat16* __restrict__ Al,
                     const __nv_bfloat16* __restrict__ BTh, const __nv_bfloat16* __restrict__ BTl,
                     const float* __restrict__ bias, float* __restrict__ C,
                     __nv_bfloat16* __restrict__ Ch, __nv_bfloat16* __restrict__ Cl,
                     int M, int N, int K) {
    extern __shared__ char smem[];
    const uint32_t sb = smem_u32(smem);
    const int tid   = threadIdx.x;
    const int lane  = tid & 31;
    const int wid   = tid >> 5;
    const int warpM = wid & 3;
    const int warpN = wid >> 2;
    const int m0 = blockIdx.y * 128;
    const int n0 = blockIdx.x * 128;
    const int nch = K / KC;

    auto load_stage = [&](int kc0, int s) {
        const uint32_t stg = sb + s * STAGE_B;
#pragma unroll
        for (int t = 0; t < 8; t++) {
            const int tile = t >> 1;
            const int rem  = tid + (t & 1) * 256;
            const int row  = rem >> 2;
            const int q    = rem & 3;
            const __nv_bfloat16* src;
            if (tile == 0)      src = Ah  + (size_t)(m0 + row) * K + kc0 + q * 8;
            else if (tile == 1) src = Al  + (size_t)(m0 + row) * K + kc0 + q * 8;
            else if (tile == 2) src = BTh + (size_t)(n0 + row) * K + kc0 + q * 8;
            else                src = BTl + (size_t)(n0 + row) * K + kc0 + q * 8;
            CP_ASYNC16(stg + tile * TILE_B + row * TROW + q * 16, src);
        }
        CP_COMMIT();
    };

    float c[2][8][4];
#pragma unroll
    for (int i = 0; i < 2; i++)
#pragma unroll
        for (int j = 0; j < 8; j++)
#pragma unroll
            for (int r = 0; r < 4; r++) c[i][j][r] = 0.0f;

    const int arow = warpM * 32 + (lane & 15);
    const int acol = (lane >> 4) * 8;
    const int brow = warpN * 64 + (lane & 7) + ((lane >> 4) << 3);
    const int bck  = ((lane >> 3) & 1) * 8;

    load_stage(0, 0);
    load_stage(KC, 1);

    for (int ch = 0; ch < nch; ch++) {
        CP_WAIT(STAGES - 2);
        __syncthreads();
        if (ch + STAGES - 1 < nch) load_stage((ch + STAGES - 1) * KC, (ch + STAGES - 1) % STAGES);
        else CP_COMMIT();

        const uint32_t stg = sb + (ch % STAGES) * STAGE_B;
        const uint32_t ahb = stg;
        const uint32_t alb = stg + TILE_B;
        const uint32_t bhb = stg + 2 * TILE_B;
        const uint32_t blb = stg + 3 * TILE_B;

#pragma unroll
        for (int k16 = 0; k16 < 2; k16++) {
            uint32_t fah[2][4], fal[2][4];
#pragma unroll
            for (int mt = 0; mt < 2; mt++) {
                uint32_t off = (uint32_t)(arow + mt * 16) * TROW + (k16 * 16 + acol) * 2;
                ldsm_x4(fah[mt][0], fah[mt][1], fah[mt][2], fah[mt][3], ahb + off);
                ldsm_x4(fal[mt][0], fal[mt][1], fal[mt][2], fal[mt][3], alb + off);
            }
            uint32_t fbh[4][4], fbl[4][4];
#pragma unroll
            for (int np = 0; np < 4; np++) {
                uint32_t off = (uint32_t)(brow + np * 16) * TROW + (k16 * 16 + bck) * 2;
                ldsm_x4(fbh[np][0], fbh[np][1], fbh[np][2], fbh[np][3], bhb + off);
                ldsm_x4(fbl[np][0], fbl[np][1], fbl[np][2], fbl[np][3], blb + off);
            }
#pragma unroll
            for (int mt = 0; mt < 2; mt++)
#pragma unroll
                for (int nt = 0; nt < 8; nt++) {
                    const uint32_t bh0 = fbh[nt >> 1][(nt & 1) * 2];
                    const uint32_t bh1 = fbh[nt >> 1][(nt & 1) * 2 + 1];
                    const uint32_t bl0 = fbl[nt >> 1][(nt & 1) * 2];
                    const uint32_t bl1 = fbl[nt >> 1][(nt & 1) * 2 + 1];
                    mma_bf16(c[mt][nt], fah[mt], bh0, bh1);
                    mma_bf16(c[mt][nt], fah[mt], bl0, bl1);
                    mma_bf16(c[mt][nt], fal[mt], bh0, bh1);
                }
        }
        __syncthreads();
    }

    const int g   = lane >> 2;
    const int tig = lane & 3;
#pragma unroll
    for (int mt = 0; mt < 2; mt++) {
        const int row = m0 + warpM * 32 + mt * 16 + g;
#pragma unroll
        for (int nt = 0; nt < 8; nt++) {
            const int col = n0 + warpN * 64 + nt * 8 + tig * 2;
            if (MODE == 1) {
                float2 v0 = make_float2(c[mt][nt][0] + bias[col], c[mt][nt][1] + bias[col + 1]);
                float2 v1 = make_float2(c[mt][nt][2] + bias[col], c[mt][nt][3] + bias[col + 1]);
                *(float2*)(C + (size_t)row * N + col)       = v0;
                *(float2*)(C + (size_t)(row + 8) * N + col) = v1;
            } else {
                const float sc = (col < HID) ? QSF : 1.0f;   // Q pre-scale (exact in fp32)
                uint32_t hp, lp;
                split_pack(c[mt][nt][0] * sc, c[mt][nt][1] * sc, hp, lp);
                *(uint32_t*)(Ch + (size_t)row * N + col) = hp;
                *(uint32_t*)(Cl + (size_t)row * N + col) = lp;
                split_pack(c[mt][nt][2] * sc, c[mt][nt][3] * sc, hp, lp);
                *(uint32_t*)(Ch + (size_t)(row + 8) * N + col) = hp;
                *(uint32_t*)(Cl + (size_t)(row + 8) * N + col) = lp;
            }
        }
    }
}

// ---------------------------------------------------------------------------
// mma.sync flash attention (bf16x3 for both QK^T and PV).
// CTA = (b, h, 128 q-rows). 8 warps x 16 q-rows. 64-key tiles, double-buffered
// cp.async hi/lo K and V. Q fragments register-resident (pre-scaled by
// 0.125*log2e in the QKV epilogue -> softmax uses raw ex2).
// ---------------------------------------------------------------------------
#define ATROW 144
#define ATILE (64 * ATROW)           // 9216
#define ASTAGE (4 * ATILE)           // 36864: Kh | Kl | Vh | Vl
#define ATT_SMEM (2 * ASTAGE + 144)  // + active-tile list

__global__ __launch_bounds__(256, 1)
void mma_attn_kernel(const __nv_bfloat16* __restrict__ Qh, const __nv_bfloat16* __restrict__ Ql,
                     __nv_bfloat16* __restrict__ Oh, __nv_bfloat16* __restrict__ Ol) {
    extern __shared__ char sm[];
    const uint32_t sb = smem_u32(sm);
    int* list = (int*)(sm + 2 * ASTAGE);   // [0..31] tiles, [32] count

    const int tid  = threadIdx.x;
    const int lane = tid & 31;
    const int w    = tid >> 5;
    const int b    = blockIdx.z;
    const int h    = blockIdx.y;
    const int q0   = blockIdx.x * 128;
    const int g    = lane >> 2;
    const int tq   = lane & 3;

    // active key-tile list (skip fully-masked tiles)
    if (w == 0) {
        unsigned long long mb = g_mbits[b * 32 + lane];
        unsigned act = __ballot_sync(0xffffffffu, mb != 0ull);
        int pos = __popc(act & ((1u << lane) - 1));
        if (mb != 0ull) list[pos] = lane;
        if (lane == 0) list[32] = __popc(act);
    }
    __syncthreads();
    const int ncnt = list[32];

    // Q fragments (register-resident): rows q0 + w*16 + {g, g+8}
    uint32_t qfh[4][4], qfl[4][4];
    {
        const size_t qb = (size_t)(b * SEQ + q0 + w * 16) * QKV3 + h * HD;
#pragma unroll
        for (int kd = 0; kd < 4; kd++) {
            const int cc = kd * 16 + tq * 2;
            qfh[kd][0] = *(const uint32_t*)(Qh + qb + (size_t)g * QKV3 + cc);
            qfh[kd][1] = *(const uint32_t*)(Qh + qb + (size_t)(g + 8) * QKV3 + cc);
            qfh[kd][2] = *(const uint32_t*)(Qh + qb + (size_t)g * QKV3 + cc + 8);
            qfh[kd][3] = *(const uint32_t*)(Qh + qb + (size_t)(g + 8) * QKV3 + cc + 8);
            qfl[kd][0] = *(const uint32_t*)(Ql + qb + (size_t)g * QKV3 + cc);
            qfl[kd][1] = *(const uint32_t*)(Ql + qb + (size_t)(g + 8) * QKV3 + cc);
            qfl[kd][2] = *(const uint32_t*)(Ql + qb + (size_t)g * QKV3 + cc + 8);
            qfl[kd][3] = *(const uint32_t*)(Ql + qb + (size_t)(g + 8) * QKV3 + cc + 8);
        }
    }

    auto load_tile = [&](int kt, int stg) {
        const int tok0 = b * SEQ + kt * 64;
        const uint32_t base = sb + stg * ASTAGE;
#pragma unroll
        for (int t = 0; t < 8; t++) {
            const int id  = tid + t * 256;
            const int arr = id >> 9;
            const int rem = id & 511;
            const int r   = rem >> 3;
            const int q   = rem & 7;
            const size_t go = (size_t)(tok0 + r) * QKV3 + h * HD + q * 8;
            const __nv_bfloat16* src;
            if (arr == 0)      src = Qh + go + HID;       // Kh
            else if (arr == 1) src = Ql + go + HID;       // Kl
            else if (arr == 2) src = Qh + go + 2 * HID;   // Vh
            else               src = Ql + go + 2 * HID;   // Vl
            CP_ASYNC16(base + arr * ATILE + r * ATROW + q * 16, src);
        }
        CP_COMMIT();
    };

    float o[8][4];
#pragma unroll
    for (int j = 0; j < 8; j++)
#pragma unroll
        for (int r = 0; r < 4; r++) o[j][r] = 0.0f;
    float mi[2] = {-1e30f, -1e30f}, li[2] = {0.0f, 0.0f};

    if (ncnt > 0) load_tile(list[0], 0);

    for (int it = 0; it < ncnt; it++) {
        if (it + 1 < ncnt) { load_tile(list[it + 1], (it + 1) & 1); CP_WAIT(1); }
        else CP_WAIT(0);
        __syncthreads();
        const uint32_t st = sb + (it & 1) * ASTAGE;
        const int kt = list[it];

        // ---- S = Q @ K^T (3-term) ----
        float s[8][4];
#pragma unroll
        for (int j = 0; j < 8; j++)
#pragma unroll
            for (int r = 0; r < 4; r++) s[j][r] = 0.0f;

#pragma unroll
        for (int kd = 0; kd < 4; kd++) {
#pragma unroll
            for (int kg = 0; kg < 4; kg++) {
                uint32_t kh[4], kl[4];
                const uint32_t off = st + (uint32_t)(kg * 16 + (lane & 7) + ((lane >> 4) << 3)) * ATROW
                                        + (kd * 16 + ((lane >> 3) & 1) * 8) * 2;
                ldsm_x4(kh[0], kh[1], kh[2], kh[3], off);
                ldsm_x4(kl[0], kl[1], kl[2], kl[3], off + ATILE);
                mma_bf16(s[kg * 2],     qfh[kd], kh[0], kh[1]);
                mma_bf16(s[kg * 2],     qfh[kd], kl[0], kl[1]);
                mma_bf16(s[kg * 2],     qfl[kd], kh[0], kh[1]);
                mma_bf16(s[kg * 2 + 1], qfh[kd], kh[2], kh[3]);
                mma_bf16(s[kg * 2 + 1], qfh[kd], kl[2], kl[3]);
                mma_bf16(s[kg * 2 + 1], qfl[kd], kh[2], kh[3]);
            }
        }

        // ---- key-padding mask ----
        const unsigned long long mb = g_mbits[b * 32 + kt];
        if (mb != ~0ull) {
#pragma unroll
            for (int nf = 0; nf < 8; nf++) {
                const int c0 = nf * 8 + tq * 2;
                if (!((mb >> c0) & 1))       { s[nf][0] = -1e30f; s[nf][2] = -1e30f; }
                if (!((mb >> (c0 + 1)) & 1)) { s[nf][1] = -1e30f; s[nf][3] = -1e30f; }
            }
        }

        // ---- online softmax (base-2 domain; Q pre-scaled) ----
#pragma unroll
        for (int r = 0; r < 2; r++) {
            float mx = -1e30f;
#pragma unroll
            for (int nf = 0; nf < 8; nf++)
                mx = fmaxf(mx, fmaxf(s[nf][2 * r], s[nf][2 * r + 1]));
            mx = fmaxf(mx, __shfl_xor_sync(0xffffffffu, mx, 1));
            mx = fmaxf(mx, __shfl_xor_sync(0xffffffffu, mx, 2));
            const float mnew = fmaxf(mi[r], mx);
            const float al = fexp2(mi[r] - mnew);
            mi[r] = mnew;
            li[r] *= al;
#pragma unroll
            for (int nf = 0; nf < 8; nf++) { o[nf][2 * r] *= al; o[nf][2 * r + 1] *= al; }
            float ls = 0.0f;
#pragma unroll
            for (int nf = 0; nf < 8; nf++) {
                const float p0 = fexp2(s[nf][2 * r] - mnew);
                const float p1 = fexp2(s[nf][2 * r + 1] - mnew);
                ls += p0 + p1;
                s[nf][2 * r] = p0;
                s[nf][2 * r + 1] = p1;
            }
            ls += __shfl_xor_sync(0xffffffffu, ls, 1);
            ls += __shfl_xor_sync(0xffffffffu, ls, 2);
            li[r] += ls;
        }

        // ---- pack P into A-fragments (hi/lo) ----
        uint32_t pah[4][4], pal[4][4];
#pragma unroll
        for (int ks = 0; ks < 4; ks++) {
            split_pack(s[2 * ks][0],     s[2 * ks][1],     pah[ks][0], pal[ks][0]);
            split_pack(s[2 * ks][2],     s[2 * ks][3],     pah[ks][1], pal[ks][1]);
            split_pack(s[2 * ks + 1][0], s[2 * ks + 1][1], pah[ks][2], pal[ks][2]);
            split_pack(s[2 * ks + 1][2], s[2 * ks + 1][3], pah[ks][3], pal[ks][3]);
        }

        // ---- O += P @ V (3-term; V fragments via ldmatrix.trans) ----
#pragma unroll
        for (int ks = 0; ks < 4; ks++) {
#pragma unroll
            for (int dg = 0; dg < 4; dg++) {
                uint32_t vh[4], vl[4];
                const uint32_t off = st + 2 * ATILE
                                   + (uint32_t)(ks * 16 + (lane & 15)) * ATROW
                                   + (dg * 16 + ((lane >> 4) << 3)) * 2;
                ldsm_x4t(vh[0], vh[1], vh[2], vh[3], off);
                ldsm_x4t(vl[0], vl[1], vl[2], vl[3], off + ATILE);
                mma_bf16(o[dg * 2],     pah[ks], vh[0], vh[1]);
                mma_bf16(o[dg * 2],     pah[ks], vl[0], vl[1]);
                mma_bf16(o[dg * 2],     pal[ks], vh[0], vh[1]);
                mma_bf16(o[dg * 2 + 1], pah[ks], vh[2], vh[3]);
                mma_bf16(o[dg * 2 + 1], pah[ks], vl[2], vl[3]);
                mma_bf16(o[dg * 2 + 1], pal[ks], vh[2], vh[3]);
            }
        }
        __syncthreads();   // protect stage buffer before next prefetch overwrite
    }

    // ---- epilogue: normalize, split to bf16 hi/lo ----
#pragma unroll
    for (int r = 0; r < 2; r++) {
        const float inv = 1.0f / li[r];
        const size_t ob = (size_t)(b * SEQ + q0 + w * 16 + g + r * 8) * HID + h * HD;
#pragma unroll
        for (int nf = 0; nf < 8; nf++) {
            uint32_t hp, lp;
            split_pack(o[nf][2 * r] * inv, o[nf][2 * r + 1] * inv, hp, lp);
            *(uint32_t*)(Oh + ob + nf * 8 + tq * 2) = hp;
            *(uint32_t*)(Ol + ob + nf * 8 + tq * 2) = lp;
        }
    }
}

// ---------------------------------------------------------------------------
// Launch
// ---------------------------------------------------------------------------
extern "C" void kernel_launch(void* const* d_in, const int* in_sizes, int n_in,
                              void* d_out, int out_size) {
    const float* hidden = (const float*)d_in[0];
    const void*  maskp  = d_in[1];
    const float* Wqkv   = (const float*)d_in[2];
    const float* Wout   = (const float*)d_in[3];
    const float* bout   = (const float*)d_in[4];
    float*       out    = (float*)d_out;

    void *p_qh, *p_ql, *p_sh, *p_sl, *p_wh, *p_wl;
    cudaGetSymbolAddress(&p_qh, g_qh);
    cudaGetSymbolAddress(&p_ql, g_ql);
    cudaGetSymbolAddress(&p_sh, g_sh);
    cudaGetSymbolAddress(&p_sl, g_sl);
    cudaGetSymbolAddress(&p_wh, g_wh);
    cudaGetSymbolAddress(&p_wl, g_wl);

    cudaFuncSetAttribute(mma_gemm_kernel<0>,
                         cudaFuncAttributeMaxDynamicSharedMemorySize, TC_SMEM);
    cudaFuncSetAttribute(mma_gemm_kernel<1>,
                         cudaFuncAttributeMaxDynamicSharedMemorySize, TC_SMEM);
    cudaFuncSetAttribute(mma_attn_kernel,
                         cudaFuncAttributeMaxDynamicSharedMemorySize, ATT_SMEM);

    // 1. mask canonicalize + tile bitmasks
    mask_convert_kernel<<<1, 256>>>(maskp, BATCH * SEQ);

    // 2. split inputs to bf16 hi/lo
    splitA_kernel<<<592, 256>>>(hidden, (__nv_bfloat16*)p_sh, (__nv_bfloat16*)p_sl,
                                MROWS * HID / 4);
    splitBT_kernel<<<dim3(QKV3 / 32, HID / 32), 256>>>(
        Wqkv, (__nv_bfloat16*)p_wh, (__nv_bfloat16*)p_wl, HID, QKV3);
    splitBT_kernel<<<dim3(HID / 32, HID / 32), 256>>>(
        Wout, (__nv_bfloat16*)p_wh + (size_t)QKV3 * HID,
        (__nv_bfloat16*)p_wl + (size_t)QKV3 * HID, HID, HID);

    // 3. QKV projection -> bf16 hi/lo splits (Q pre-scaled by 0.125*log2e)
    mma_gemm_kernel<0><<<dim3(QKV3 / 128, MROWS / 128), 256, TC_SMEM>>>(
        (const __nv_bfloat16*)p_sh, (const __nv_bfloat16*)p_sl,
        (const __nv_bfloat16*)p_wh, (const __nv_bfloat16*)p_wl,
        nullptr, nullptr, (__nv_bfloat16*)p_qh, (__nv_bfloat16*)p_ql,
        MROWS, QKV3, HID);

    // 4. tensor-core flash attention -> bf16 hi/lo attention output
    mma_attn_kernel<<<dim3(SEQ / 128, NH, BATCH), 256, ATT_SMEM>>>(
        (const __nv_bfloat16*)p_qh, (const __nv_bfloat16*)p_ql,
        (__nv_bfloat16*)p_sh, (__nv_bfloat16*)p_sl);

    // 5. output projection (+bias)
    mma_gemm_kernel<1><<<dim3(HID / 128, MROWS / 128), 256, TC_SMEM>>>(
        (const __nv_bfloat16*)p_sh, (const __nv_bfloat16*)p_sl,
        (const __nv_bfloat16*)p_wh + (size_t)QKV3 * HID,
        (const __nv_bfloat16*)p_wl + (size_t)QKV3 * HID,
        bout, out, nullptr, nullptr, MROWS, HID, HID);
}

// round 5
// speedup vs baseline: 3.1957x; 1.1086x over previous
#include <cuda_runtime.h>
#include <cuda_bf16.h>
#include <cstdint>

#define BATCH 4
#define SEQ   2048
#define NH    16
#define HD    64
#define HID   1024
#define QKV3  3072
#define MROWS (BATCH * SEQ)        // 8192

// 0.125 * log2(e): folded into Q at the QKV epilogue (softmax in base-2 domain)
#define QSF 0.18033688011112042f

// ---------------------------------------------------------------------------
// Scratch (static device globals — allocation-free per harness rules)
// ---------------------------------------------------------------------------
__device__ __nv_bfloat16 g_qh[MROWS * QKV3];           // qkv hi split (48 MB)
__device__ __nv_bfloat16 g_ql[MROWS * QKV3];           // qkv lo split
__device__ int           g_mask[BATCH * SEQ];
__device__ unsigned long long g_mbits[BATCH * 32];     // 64-key tile bitmasks
__device__ __nv_bfloat16 g_sh[MROWS * HID];            // activation hi (hidden, then attn out)
__device__ __nv_bfloat16 g_sl[MROWS * HID];            // activation lo
__device__ __nv_bfloat16 g_wh[(QKV3 + HID) * HID];     // W^T hi
__device__ __nv_bfloat16 g_wl[(QKV3 + HID) * HID];     // W^T lo

// ---------------------------------------------------------------------------
// PTX helpers (arch-portable sm_80+; tcgen05 unavailable via compute_103)
// ---------------------------------------------------------------------------
__device__ __forceinline__ uint32_t smem_u32(const void* p) {
    uint32_t a;
    asm("{ .reg .u64 t; cvta.to.shared.u64 t, %1; cvt.u32.u64 %0, t; }" : "=r"(a) : "l"(p));
    return a;
}
__device__ __forceinline__ void ldsm_x4(uint32_t& r0, uint32_t& r1, uint32_t& r2, uint32_t& r3,
                                        uint32_t addr) {
    asm volatile("ldmatrix.sync.aligned.m8n8.x4.shared.b16 {%0,%1,%2,%3}, [%4];"
                 : "=r"(r0), "=r"(r1), "=r"(r2), "=r"(r3) : "r"(addr));
}
__device__ __forceinline__ void ldsm_x4t(uint32_t& r0, uint32_t& r1, uint32_t& r2, uint32_t& r3,
                                         uint32_t addr) {
    asm volatile("ldmatrix.sync.aligned.m8n8.x4.trans.shared.b16 {%0,%1,%2,%3}, [%4];"
                 : "=r"(r0), "=r"(r1), "=r"(r2), "=r"(r3) : "r"(addr));
}
__device__ __forceinline__ void mma_bf16(float* c, const uint32_t* a, uint32_t b0, uint32_t b1) {
    asm volatile(
        "mma.sync.aligned.m16n8k16.row.col.f32.bf16.bf16.f32 "
        "{%0,%1,%2,%3}, {%4,%5,%6,%7}, {%8,%9}, {%0,%1,%2,%3};"
        : "+f"(c[0]), "+f"(c[1]), "+f"(c[2]), "+f"(c[3])
        : "r"(a[0]), "r"(a[1]), "r"(a[2]), "r"(a[3]), "r"(b0), "r"(b1));
}
__device__ __forceinline__ float fexp2(float x) {
    float y; asm("ex2.approx.f32 %0, %1;" : "=f"(y) : "f"(x)); return y;
}
__device__ __forceinline__ void split_pack(float x, float y, uint32_t& hp, uint32_t& lp) {
    __nv_bfloat162 hv, lv;
    hv.x = __float2bfloat16(x);
    hv.y = __float2bfloat16(y);
    lv.x = __float2bfloat16(x - __bfloat162float(hv.x));
    lv.y = __float2bfloat16(y - __bfloat162float(hv.y));
    hp = *(uint32_t*)&hv;
    lp = *(uint32_t*)&lv;
}
#define CP_ASYNC16(dst, src) \
    asm volatile("cp.async.cg.shared.global [%0], [%1], 16;" :: "r"(dst), "l"(src))
#define CP_COMMIT() asm volatile("cp.async.commit_group;" ::: "memory")
#define CP_WAIT(n)  asm volatile("cp.async.wait_group %0;" :: "n"(n) : "memory")

// ---------------------------------------------------------------------------
// Mask canonicalizer + per-64-key-tile bitmasks
// ---------------------------------------------------------------------------
__global__ void mask_convert_kernel(const void* __restrict__ raw, int n) {
    __shared__ int mode;
    if (threadIdx.x == 0) {
        unsigned w0 = ((const unsigned*)raw)[0];
        if (w0 == 1u || w0 == 0u)    mode = 0;  // int32
        else if (w0 == 0x3F800000u)  mode = 1;  // float32
        else if (w0 == 0x01010101u)  mode = 2;  // uint8
        else if (w0 == 0x3F803F80u)  mode = 3;  // bf16 pair
        else                          mode = 2;
    }
    __syncthreads();
    int m = mode;
    for (int i = threadIdx.x; i < n; i += blockDim.x) {
        int v;
        if (m == 0)      v = (((const int*)raw)[i] != 0);
        else if (m == 1) v = (((const float*)raw)[i] != 0.0f);
        else if (m == 2) v = (((const unsigned char*)raw)[i] != 0);
        else { unsigned short h = ((const unsigned short*)raw)[i]; v = ((h & 0x7FFF) != 0); }
        g_mask[i] = v;
    }
    __syncthreads();
    for (int t = threadIdx.x; t < BATCH * 32; t += blockDim.x) {
        int b = t >> 5, kt = t & 31;
        unsigned long long mb = 0ull;
        for (int j = 0; j < 64; j++)
            mb |= ((unsigned long long)(g_mask[b * SEQ + kt * 64 + j] & 1)) << j;
        g_mbits[t] = mb;
    }
}

// ---------------------------------------------------------------------------
// bf16 split kernels (hidden input + weights)
// ---------------------------------------------------------------------------
__global__ void splitA_kernel(const float* __restrict__ A,
                              __nv_bfloat16* __restrict__ Ah,
                              __nv_bfloat16* __restrict__ Al, int n4) {
    int stride = gridDim.x * blockDim.x;
    for (int i = blockIdx.x * blockDim.x + threadIdx.x; i < n4; i += stride) {
        float4 v = ((const float4*)A)[i];
        uint32_t h0, l0, h1, l1;
        split_pack(v.x, v.y, h0, l0);
        split_pack(v.z, v.w, h1, l1);
        ((uint32_t*)Ah)[i * 2]     = h0;
        ((uint32_t*)Ah)[i * 2 + 1] = h1;
        ((uint32_t*)Al)[i * 2]     = l0;
        ((uint32_t*)Al)[i * 2 + 1] = l1;
    }
}

// B [K,N] fp32 -> B^T [N,K] bf16 hi/lo
__global__ void splitBT_kernel(const float* __restrict__ B,
                               __nv_bfloat16* __restrict__ BTh,
                               __nv_bfloat16* __restrict__ BTl, int K, int N) {
    __shared__ float tile[32][33];
    int k0 = blockIdx.y * 32, n0 = blockIdx.x * 32;
    int tx = threadIdx.x & 31, ty = threadIdx.x >> 5;
    for (int r = ty; r < 32; r += 8)
        tile[r][tx] = B[(size_t)(k0 + r) * N + n0 + tx];
    __syncthreads();
    for (int r = ty; r < 32; r += 8) {
        float v = tile[tx][r];
        __nv_bfloat16 h = __float2bfloat16(v);
        __nv_bfloat16 l = __float2bfloat16(v - __bfloat162float(h));
        size_t o = (size_t)(n0 + r) * K + k0 + tx;
        BTh[o] = h;
        BTl[o] = l;
    }
}

// ---------------------------------------------------------------------------
// mma.sync bf16x3 GEMM. 2-stage cp.async, 2 CTAs/SM (regs capped at 128).
// MODE 0: bf16 hi/lo output + Q-scale on cols < HID. MODE 1: fp32 + bias.
// ---------------------------------------------------------------------------
#define KC        32
#define TROW      80
#define TILE_B    (128 * TROW)
#define STAGE_B   (4 * TILE_B)          // 40960: Ah | Al | Bh | Bl
#define TC_SMEM   (2 * STAGE_B)         // 81920 -> 2 CTAs/SM

template <int MODE>
__global__ __launch_bounds__(256, 2)
void mma_gemm_kernel(const __nv_bfloat16* __restrict__ Ah, const __nv_bfloat16* __restrict__ Al,
                     const __nv_bfloat16* __restrict__ BTh, const __nv_bfloat16* __restrict__ BTl,
                     const float* __restrict__ bias, float* __restrict__ C,
                     __nv_bfloat16* __restrict__ Ch, __nv_bfloat16* __restrict__ Cl,
                     int M, int N, int K) {
    extern __shared__ char smem[];
    const uint32_t sb = smem_u32(smem);
    const int tid   = threadIdx.x;
    const int lane  = tid & 31;
    const int wid   = tid >> 5;
    const int warpM = wid & 3;
    const int warpN = wid >> 2;
    const int m0 = blockIdx.y * 128;
    const int n0 = blockIdx.x * 128;
    const int nch = K / KC;

    auto load_stage = [&](int kc0, int s) {
        const uint32_t stg = sb + s * STAGE_B;
#pragma unroll
        for (int t = 0; t < 8; t++) {
            const int tile = t >> 1;
            const int rem  = tid + (t & 1) * 256;
            const int row  = rem >> 2;
            const int q    = rem & 3;
            const __nv_bfloat16* src;
            if (tile == 0)      src = Ah  + (size_t)(m0 + row) * K + kc0 + q * 8;
            else if (tile == 1) src = Al  + (size_t)(m0 + row) * K + kc0 + q * 8;
            else if (tile == 2) src = BTh + (size_t)(n0 + row) * K + kc0 + q * 8;
            else                src = BTl + (size_t)(n0 + row) * K + kc0 + q * 8;
            CP_ASYNC16(stg + tile * TILE_B + row * TROW + q * 16, src);
        }
        CP_COMMIT();
    };

    float c[2][8][4];
#pragma unroll
    for (int i = 0; i < 2; i++)
#pragma unroll
        for (int j = 0; j < 8; j++)
#pragma unroll
            for (int r = 0; r < 4; r++) c[i][j][r] = 0.0f;

    const int arow = warpM * 32 + (lane & 15);
    const int acol = (lane >> 4) * 8;
    const int brow = warpN * 64 + (lane & 7) + ((lane >> 4) << 3);
    const int bck  = ((lane >> 3) & 1) * 8;

    load_stage(0, 0);
    load_stage(KC, 1);

    for (int ch = 0; ch < nch; ch++) {
        CP_WAIT(1);
        __syncthreads();

        const uint32_t stg = sb + (ch & 1) * STAGE_B;
        const uint32_t ahb = stg;
        const uint32_t alb = stg + TILE_B;
        const uint32_t bhb = stg + 2 * TILE_B;
        const uint32_t blb = stg + 3 * TILE_B;

#pragma unroll
        for (int k16 = 0; k16 < 2; k16++) {
            uint32_t fah[2][4], fal[2][4];
#pragma unroll
            for (int mt = 0; mt < 2; mt++) {
                uint32_t off = (uint32_t)(arow + mt * 16) * TROW + (k16 * 16 + acol) * 2;
                ldsm_x4(fah[mt][0], fah[mt][1], fah[mt][2], fah[mt][3], ahb + off);
                ldsm_x4(fal[mt][0], fal[mt][1], fal[mt][2], fal[mt][3], alb + off);
            }
#pragma unroll
            for (int np = 0; np < 4; np++) {
                uint32_t bh[4], bl[4];
                uint32_t off = (uint32_t)(brow + np * 16) * TROW + (k16 * 16 + bck) * 2;
                ldsm_x4(bh[0], bh[1], bh[2], bh[3], bhb + off);
                ldsm_x4(bl[0], bl[1], bl[2], bl[3], blb + off);
#pragma unroll
                for (int mt = 0; mt < 2; mt++)
#pragma unroll
                    for (int half = 0; half < 2; half++) {
                        float* acc = c[mt][np * 2 + half];
                        mma_bf16(acc, fah[mt], bh[half * 2], bh[half * 2 + 1]);
                        mma_bf16(acc, fah[mt], bl[half * 2], bl[half * 2 + 1]);
                        mma_bf16(acc, fal[mt], bh[half * 2], bh[half * 2 + 1]);
                    }
            }
        }
        __syncthreads();
        if (ch + 2 < nch) load_stage((ch + 2) * KC, ch & 1);
        else CP_COMMIT();   // placeholder group: keeps CP_WAIT(1) accounting exact
    }

    const int g   = lane >> 2;
    const int tig = lane & 3;
#pragma unroll
    for (int mt = 0; mt < 2; mt++) {
        const int row = m0 + warpM * 32 + mt * 16 + g;
#pragma unroll
        for (int nt = 0; nt < 8; nt++) {
            const int col = n0 + warpN * 64 + nt * 8 + tig * 2;
            if (MODE == 1) {
                float2 v0 = make_float2(c[mt][nt][0] + bias[col], c[mt][nt][1] + bias[col + 1]);
                float2 v1 = make_float2(c[mt][nt][2] + bias[col], c[mt][nt][3] + bias[col + 1]);
                *(float2*)(C + (size_t)row * N + col)       = v0;
                *(float2*)(C + (size_t)(row + 8) * N + col) = v1;
            } else {
                const float sc = (col < HID) ? QSF : 1.0f;
                uint32_t hp, lp;
                split_pack(c[mt][nt][0] * sc, c[mt][nt][1] * sc, hp, lp);
                *(uint32_t*)(Ch + (size_t)row * N + col) = hp;
                *(uint32_t*)(Cl + (size_t)row * N + col) = lp;
                split_pack(c[mt][nt][2] * sc, c[mt][nt][3] * sc, hp, lp);
                *(uint32_t*)(Ch + (size_t)(row + 8) * N + col) = hp;
                *(uint32_t*)(Cl + (size_t)(row + 8) * N + col) = lp;
            }
        }
    }
}

// ---------------------------------------------------------------------------
// mma.sync flash attention (bf16x3 both products). R4-proven core.
// ---------------------------------------------------------------------------
#define ATROW 144
#define ATILE (64 * ATROW)           // 9216
#define ASTAGE (4 * ATILE)           // 36864: Kh | Kl | Vh | Vl
#define ATT_SMEM (2 * ASTAGE + 144)

__global__ __launch_bounds__(256, 1)
void mma_attn_kernel(const __nv_bfloat16* __restrict__ Qh, const __nv_bfloat16* __restrict__ Ql,
                     __nv_bfloat16* __restrict__ Oh, __nv_bfloat16* __restrict__ Ol) {
    extern __shared__ char sm[];
    const uint32_t sb = smem_u32(sm);
    int* list = (int*)(sm + 2 * ASTAGE);

    const int tid  = threadIdx.x;
    const int lane = tid & 31;
    const int w    = tid >> 5;
    const int b    = blockIdx.z;
    const int h    = blockIdx.y;
    const int q0   = blockIdx.x * 128;
    const int g    = lane >> 2;
    const int tq   = lane & 3;

    if (w == 0) {
        unsigned long long mb = g_mbits[b * 32 + lane];
        unsigned act = __ballot_sync(0xffffffffu, mb != 0ull);
        int pos = __popc(act & ((1u << lane) - 1));
        if (mb != 0ull) list[pos] = lane;
        if (lane == 0) list[32] = __popc(act);
    }
    __syncthreads();
    const int ncnt = list[32];

    uint32_t qfh[4][4], qfl[4][4];
    {
        const size_t qb = (size_t)(b * SEQ + q0 + w * 16) * QKV3 + h * HD;
#pragma unroll
        for (int kd = 0; kd < 4; kd++) {
            const int cc = kd * 16 + tq * 2;
            qfh[kd][0] = *(const uint32_t*)(Qh + qb + (size_t)g * QKV3 + cc);
            qfh[kd][1] = *(const uint32_t*)(Qh + qb + (size_t)(g + 8) * QKV3 + cc);
            qfh[kd][2] = *(const uint32_t*)(Qh + qb + (size_t)g * QKV3 + cc + 8);
            qfh[kd][3] = *(const uint32_t*)(Qh + qb + (size_t)(g + 8) * QKV3 + cc + 8);
            qfl[kd][0] = *(const uint32_t*)(Ql + qb + (size_t)g * QKV3 + cc);
            qfl[kd][1] = *(const uint32_t*)(Ql + qb + (size_t)(g + 8) * QKV3 + cc);
            qfl[kd][2] = *(const uint32_t*)(Ql + qb + (size_t)g * QKV3 + cc + 8);
            qfl[kd][3] = *(const uint32_t*)(Ql + qb + (size_t)(g + 8) * QKV3 + cc + 8);
        }
    }

    auto load_tile = [&](int kt, int stg) {
        const int tok0 = b * SEQ + kt * 64;
        const uint32_t base = sb + stg * ASTAGE;
#pragma unroll
        for (int t = 0; t < 8; t++) {
            const int id  = tid + t * 256;
            const int arr = id >> 9;
            const int rem = id & 511;
            const int r   = rem >> 3;
            const int q   = rem & 7;
            const size_t go = (size_t)(tok0 + r) * QKV3 + h * HD + q * 8;
            const __nv_bfloat16* src;
            if (arr == 0)      src = Qh + go + HID;
            else if (arr == 1) src = Ql + go + HID;
            else if (arr == 2) src = Qh + go + 2 * HID;
            else               src = Ql + go + 2 * HID;
            CP_ASYNC16(base + arr * ATILE + r * ATROW + q * 16, src);
        }
        CP_COMMIT();
    };

    float o[8][4];
#pragma unroll
    for (int j = 0; j < 8; j++)
#pragma unroll
        for (int r = 0; r < 4; r++) o[j][r] = 0.0f;
    float mi[2] = {-1e30f, -1e30f}, li[2] = {0.0f, 0.0f};

    if (ncnt > 0) load_tile(list[0], 0);

    for (int it = 0; it < ncnt; it++) {
        if (it + 1 < ncnt) { load_tile(list[it + 1], (it + 1) & 1); CP_WAIT(1); }
        else CP_WAIT(0);
        __syncthreads();
        const uint32_t st = sb + (it & 1) * ASTAGE;
        const int kt = list[it];

        float s[8][4];
#pragma unroll
        for (int j = 0; j < 8; j++)
#pragma unroll
            for (int r = 0; r < 4; r++) s[j][r] = 0.0f;

#pragma unroll
        for (int kd = 0; kd < 4; kd++) {
#pragma unroll
            for (int kg = 0; kg < 4; kg++) {
                uint32_t kh[4], kl[4];
                const uint32_t off = st + (uint32_t)(kg * 16 + (lane & 7) + ((lane >> 4) << 3)) * ATROW
                                        + (kd * 16 + ((lane >> 3) & 1) * 8) * 2;
                ldsm_x4(kh[0], kh[1], kh[2], kh[3], off);
                ldsm_x4(kl[0], kl[1], kl[2], kl[3], off + ATILE);
                mma_bf16(s[kg * 2],     qfh[kd], kh[0], kh[1]);
                mma_bf16(s[kg * 2],     qfh[kd], kl[0], kl[1]);
                mma_bf16(s[kg * 2],     qfl[kd], kh[0], kh[1]);
                mma_bf16(s[kg * 2 + 1], qfh[kd], kh[2], kh[3]);
                mma_bf16(s[kg * 2 + 1], qfh[kd], kl[2], kl[3]);
                mma_bf16(s[kg * 2 + 1], qfl[kd], kh[2], kh[3]);
            }
        }

        const unsigned long long mb = g_mbits[b * 32 + kt];
        if (mb != ~0ull) {
#pragma unroll
            for (int nf = 0; nf < 8; nf++) {
                const int c0 = nf * 8 + tq * 2;
                if (!((mb >> c0) & 1))       { s[nf][0] = -1e30f; s[nf][2] = -1e30f; }
                if (!((mb >> (c0 + 1)) & 1)) { s[nf][1] = -1e30f; s[nf][3] = -1e30f; }
            }
        }

#pragma unroll
        for (int r = 0; r < 2; r++) {
            float mx = -1e30f;
#pragma unroll
            for (int nf = 0; nf < 8; nf++)
                mx = fmaxf(mx, fmaxf(s[nf][2 * r], s[nf][2 * r + 1]));
            mx = fmaxf(mx, __shfl_xor_sync(0xffffffffu, mx, 1));
            mx = fmaxf(mx, __shfl_xor_sync(0xffffffffu, mx, 2));
            const float mnew = fmaxf(mi[r], mx);
            const float al = fexp2(mi[r] - mnew);
            mi[r] = mnew;
            li[r] *= al;
#pragma unroll
            for (int nf = 0; nf < 8; nf++) { o[nf][2 * r] *= al; o[nf][2 * r + 1] *= al; }
            float ls = 0.0f;
#pragma unroll
            for (int nf = 0; nf < 8; nf++) {
                const float p0 = fexp2(s[nf][2 * r] - mnew);
                const float p1 = fexp2(s[nf][2 * r + 1] - mnew);
                ls += p0 + p1;
                s[nf][2 * r] = p0;
                s[nf][2 * r + 1] = p1;
            }
            ls += __shfl_xor_sync(0xffffffffu, ls, 1);
            ls += __shfl_xor_sync(0xffffffffu, ls, 2);
            li[r] += ls;
        }

        uint32_t pah[4][4], pal[4][4];
#pragma unroll
        for (int ks = 0; ks < 4; ks++) {
            split_pack(s[2 * ks][0],     s[2 * ks][1],     pah[ks][0], pal[ks][0]);
            split_pack(s[2 * ks][2],     s[2 * ks][3],     pah[ks][1], pal[ks][1]);
            split_pack(s[2 * ks + 1][0], s[2 * ks + 1][1], pah[ks][2], pal[ks][2]);
            split_pack(s[2 * ks + 1][2], s[2 * ks + 1][3], pah[ks][3], pal[ks][3]);
        }

#pragma unroll
        for (int ks = 0; ks < 4; ks++) {
#pragma unroll
            for (int dg = 0; dg < 4; dg++) {
                uint32_t vh[4], vl[4];
                const uint32_t off = st + 2 * ATILE
                                   + (uint32_t)(ks * 16 + (lane & 15)) * ATROW
                                   + (dg * 16 + ((lane >> 4) << 3)) * 2;
                ldsm_x4t(vh[0], vh[1], vh[2], vh[3], off);
                ldsm_x4t(vl[0], vl[1], vl[2], vl[3], off + ATILE);
                mma_bf16(o[dg * 2],     pah[ks], vh[0], vh[1]);
                mma_bf16(o[dg * 2],     pah[ks], vl[0], vl[1]);
                mma_bf16(o[dg * 2],     pal[ks], vh[0], vh[1]);
                mma_bf16(o[dg * 2 + 1], pah[ks], vh[2], vh[3]);
                mma_bf16(o[dg * 2 + 1], pah[ks], vl[2], vl[3]);
                mma_bf16(o[dg * 2 + 1], pal[ks], vh[2], vh[3]);
            }
        }
        __syncthreads();
    }

#pragma unroll
    for (int r = 0; r < 2; r++) {
        const float inv = 1.0f / li[r];
        const size_t ob = (size_t)(b * SEQ + q0 + w * 16 + g + r * 8) * HID + h * HD;
#pragma unroll
        for (int nf = 0; nf < 8; nf++) {
            uint32_t hp, lp;
            split_pack(o[nf][2 * r] * inv, o[nf][2 * r + 1] * inv, hp, lp);
            *(uint32_t*)(Oh + ob + nf * 8 + tq * 2) = hp;
            *(uint32_t*)(Ol + ob + nf * 8 + tq * 2) = lp;
        }
    }
}

// ---------------------------------------------------------------------------
// Launch
// ---------------------------------------------------------------------------
extern "C" void kernel_launch(void* const* d_in, const int* in_sizes, int n_in,
                              void* d_out, int out_size) {
    const float* hidden = (const float*)d_in[0];
    const void*  maskp  = d_in[1];
    const float* Wqkv   = (const float*)d_in[2];
    const float* Wout   = (const float*)d_in[3];
    const float* bout   = (const float*)d_in[4];
    float*       out    = (float*)d_out;

    void *p_qh, *p_ql, *p_sh, *p_sl, *p_wh, *p_wl;
    cudaGetSymbolAddress(&p_qh, g_qh);
    cudaGetSymbolAddress(&p_ql, g_ql);
    cudaGetSymbolAddress(&p_sh, g_sh);
    cudaGetSymbolAddress(&p_sl, g_sl);
    cudaGetSymbolAddress(&p_wh, g_wh);
    cudaGetSymbolAddress(&p_wl, g_wl);

    cudaFuncSetAttribute(mma_gemm_kernel<0>,
                         cudaFuncAttributeMaxDynamicSharedMemorySize, TC_SMEM);
    cudaFuncSetAttribute(mma_gemm_kernel<1>,
                         cudaFuncAttributeMaxDynamicSharedMemorySize, TC_SMEM);
    cudaFuncSetAttribute(mma_attn_kernel,
                         cudaFuncAttributeMaxDynamicSharedMemorySize, ATT_SMEM);

    // 1. mask canonicalize + tile bitmasks
    mask_convert_kernel<<<1, 256>>>(maskp, BATCH * SEQ);

    // 2. split inputs to bf16 hi/lo
    splitA_kernel<<<592, 256>>>(hidden, (__nv_bfloat16*)p_sh, (__nv_bfloat16*)p_sl,
                                MROWS * HID / 4);
    splitBT_kernel<<<dim3(QKV3 / 32, HID / 32), 256>>>(
        Wqkv, (__nv_bfloat16*)p_wh, (__nv_bfloat16*)p_wl, HID, QKV3);
    splitBT_kernel<<<dim3(HID / 32, HID / 32), 256>>>(
        Wout, (__nv_bfloat16*)p_wh + (size_t)QKV3 * HID,
        (__nv_bfloat16*)p_wl + (size_t)QKV3 * HID, HID, HID);

    // 3. QKV projection -> bf16 hi/lo splits (Q pre-scaled by 0.125*log2e)
    mma_gemm_kernel<0><<<dim3(QKV3 / 128, MROWS / 128), 256, TC_SMEM>>>(
        (const __nv_bfloat16*)p_sh, (const __nv_bfloat16*)p_sl,
        (const __nv_bfloat16*)p_wh, (const __nv_bfloat16*)p_wl,
        nullptr, nullptr, (__nv_bfloat16*)p_qh, (__nv_bfloat16*)p_ql,
        MROWS, QKV3, HID);

    // 4. tensor-core flash attention -> bf16 hi/lo attention output
    mma_attn_kernel<<<dim3(SEQ / 128, NH, BATCH), 256, ATT_SMEM>>>(
        (const __nv_bfloat16*)p_qh, (const __nv_bfloat16*)p_ql,
        (__nv_bfloat16*)p_sh, (__nv_bfloat16*)p_sl);

    // 5. output projection (+bias)
    mma_gemm_kernel<1><<<dim3(HID / 128, MROWS / 128), 256, TC_SMEM>>>(
        (const __nv_bfloat16*)p_sh, (const __nv_bfloat16*)p_sl,
        (const __nv_bfloat16*)p_wh + (size_t)QKV3 * HID,
        (const __nv_bfloat16*)p_wl + (size_t)QKV3 * HID,
        bout, out, nullptr, nullptr, MROWS, HID, HID);
}